// round 2
// baseline (speedup 1.0000x reference)
#include <cuda_runtime.h>
#include <math.h>

// Problem constants (from reference): N=20000, E=640000, S=128, V=16, E_DIM=32
#define MAXN 20000

// Aggregation scratch (scatter-add targets). Static device arrays: allocation-free.
__device__ float g_agg_s[MAXN * 128];
__device__ float g_agg_v[MAXN * 48];

__device__ __forceinline__ float sigmoidf_(float x) {
    return 1.0f / (1.0f + __expf(-x));
}

// ---------------------------------------------------------------------------
// Zero the aggregation buffers
// ---------------------------------------------------------------------------
__global__ void zero_kernel(int n) {
    int total = n * 176;  // 128 + 48
    for (int i = blockIdx.x * blockDim.x + threadIdx.x; i < total;
         i += gridDim.x * blockDim.x) {
        if (i < n * 128) g_agg_s[i] = 0.0f;
        else             g_agg_v[i - n * 128] = 0.0f;
    }
}

// ---------------------------------------------------------------------------
// Edge message kernel: 32 edges per block, 256 threads.
//   x[e][0..321] = [s[src](128), s[dst](128), edge_s(32), edge_len(1), vn(33)]
//   h  = x @ W1 + b1 ; t = silu(h)
//   ms = t @ W2 + b2
//   gate = sigmoid(ms @ Wg + bg)
//   mv[w][c] = gate[w] * sum_j v_in[j][c] * Wv[j][w]   (v_in = [v_src,v_dst,ev])
//   atomicAdd into g_agg_s[dst], g_agg_v[dst]
// ---------------------------------------------------------------------------
// Shared layout (floats):
//   sxT  : [336][36]  (K-major X, e-dim padded to 36)         @ 0      (12096)
//   swt  : [16][128]  (W tile)                                @ 12096  (2048)
//   sttT : [128][36]  (silu(h) transposed)                    @ 14144  (4608)
//   sv   : [32][100]  (v inputs, 33 rows x 3)                 @ 18752  (3200)
//   sg   : [32][16]   (gates)                                 @ 21952  (512)
//   sidx : 64 ints                                            @ 22464  (64)
//   sms aliases sxT (safe: sxT dead after GEMM1)
// total = 22528 floats = 90112 bytes
#define EDGE_SMEM_BYTES (22528 * 4)

__global__ __launch_bounds__(256, 2) void edge_kernel(
    const float* __restrict__ s, const float* __restrict__ v,
    const int* __restrict__ ei, const float* __restrict__ es,
    const float* __restrict__ ev,
    const float* __restrict__ W1, const float* __restrict__ b1,
    const float* __restrict__ W2, const float* __restrict__ b2,
    const float* __restrict__ Wv, const float* __restrict__ Wg,
    const float* __restrict__ bg, int E)
{
    extern __shared__ __align__(16) float sm[];
    float* sxT  = sm;
    float* swt  = sm + 12096;
    float* sttT = sm + 14144;
    float* sv   = sm + 18752;
    float* sg   = sm + 21952;
    int*   ssrc = (int*)(sm + 22464);
    int*   sdst = ssrc + 32;
    float* sms  = sm;  // alias of sxT, used after GEMM1 completes

    const int tid = threadIdx.x;
    const int e0  = blockIdx.x * 32;
    const int nval = min(32, E - e0);

    if (tid < 32) {
        int ee = e0 + min(tid, nval - 1);
        ssrc[tid] = ei[ee];
        sdst[tid] = ei[E + ee];
    }
    __syncthreads();

    // ---- gather scalar features into transposed X ----
    for (int idx = tid; idx < 32 * 288; idx += 256) {
        int e = idx / 288;
        int k = idx - e * 288;
        int eg = e0 + (e < nval ? e : 0);
        float val;
        if (k < 128)      val = s[ssrc[e] * 128 + k];
        else if (k < 256) val = s[sdst[e] * 128 + (k - 128)];
        else              val = es[eg * 32 + (k - 256)];
        sxT[k * 36 + e] = val;
    }
    // ---- gather vector features ----
    for (int idx = tid; idx < 32 * 99; idx += 256) {
        int e = idx / 99;
        int j = idx - e * 99;
        int eg = e0 + (e < nval ? e : 0);
        float val;
        if (j < 48)      val = v[ssrc[e] * 48 + j];
        else if (j < 96) val = v[sdst[e] * 48 + (j - 48)];
        else             val = ev[eg * 3 + (j - 96)];
        sv[e * 100 + j] = val;
    }
    // zero-pad K rows 322..335
    for (int idx = tid; idx < 14 * 32; idx += 256) {
        sxT[(322 + (idx >> 5)) * 36 + (idx & 31)] = 0.0f;
    }
    __syncthreads();

    // ---- vector norms -> X rows 288..321 ----
    for (int idx = tid; idx < 32 * 33; idx += 256) {
        int e = idx / 33;
        int j = idx - e * 33;
        float a = sv[e * 100 + j * 3 + 0];
        float b = sv[e * 100 + j * 3 + 1];
        float c = sv[e * 100 + j * 3 + 2];
        float nn = sqrtf(fmaxf(a * a + b * b + c * c, 1e-8f));
        sxT[(289 + j) * 36 + e] = nn;
        if (j == 32) sxT[288 * 36 + e] = nn;  // edge_len == |edge_v|
    }
    __syncthreads();

    const int ty = tid >> 5;   // 0..7  -> edges 4*ty .. 4*ty+3
    const int tx = tid & 31;   // 0..31 -> cols  4*tx .. 4*tx+3

    float acc[4][4];
#pragma unroll
    for (int i = 0; i < 4; ++i)
#pragma unroll
        for (int j = 0; j < 4; ++j) acc[i][j] = 0.0f;

    // ---- GEMM1: K = 336 (padded), 21 tiles of 16 ----
    const float4* W14 = (const float4*)W1;
    float4* swt4 = (float4*)swt;
    for (int kt = 0; kt < 21; ++kt) {
        for (int i = tid; i < 512; i += 256) {
            int k = kt * 16 + (i >> 5);
            swt4[i] = (k < 322) ? W14[k * 32 + (i & 31)]
                                : make_float4(0.f, 0.f, 0.f, 0.f);
        }
        __syncthreads();
#pragma unroll
        for (int kk = 0; kk < 16; ++kk) {
            float4 xv = *(const float4*)&sxT[(kt * 16 + kk) * 36 + 4 * ty];
            float4 wv = *(const float4*)&swt[kk * 128 + 4 * tx];
            float xs[4] = {xv.x, xv.y, xv.z, xv.w};
            float ws[4] = {wv.x, wv.y, wv.z, wv.w};
#pragma unroll
            for (int i = 0; i < 4; ++i)
#pragma unroll
                for (int j = 0; j < 4; ++j)
                    acc[i][j] = fmaf(xs[i], ws[j], acc[i][j]);
        }
        __syncthreads();
    }

    // ---- epilogue 1: bias + silu, store transposed t ----
#pragma unroll
    for (int j = 0; j < 4; ++j) {
        float bb = b1[4 * tx + j];
#pragma unroll
        for (int i = 0; i < 4; ++i) {
            float h = acc[i][j] + bb;
            float t = h * sigmoidf_(h);
            sttT[(4 * tx + j) * 36 + 4 * ty + i] = t;
        }
    }
    __syncthreads();

    // ---- GEMM2: K = 128, 8 tiles of 16 ----
#pragma unroll
    for (int i = 0; i < 4; ++i)
#pragma unroll
        for (int j = 0; j < 4; ++j) acc[i][j] = 0.0f;

    const float4* W24 = (const float4*)W2;
    for (int kt = 0; kt < 8; ++kt) {
        for (int i = tid; i < 512; i += 256) {
            int k = kt * 16 + (i >> 5);
            swt4[i] = W24[k * 32 + (i & 31)];
        }
        __syncthreads();
#pragma unroll
        for (int kk = 0; kk < 16; ++kk) {
            float4 xv = *(const float4*)&sttT[(kt * 16 + kk) * 36 + 4 * ty];
            float4 wv = *(const float4*)&swt[kk * 128 + 4 * tx];
            float xs[4] = {xv.x, xv.y, xv.z, xv.w};
            float ws[4] = {wv.x, wv.y, wv.z, wv.w};
#pragma unroll
            for (int i = 0; i < 4; ++i)
#pragma unroll
                for (int j = 0; j < 4; ++j)
                    acc[i][j] = fmaf(xs[i], ws[j], acc[i][j]);
        }
        __syncthreads();
    }

    // ---- epilogue 2: bias, scatter-add m_s, keep m_s in smem for gate ----
#pragma unroll
    for (int j = 0; j < 4; ++j) {
        int c = 4 * tx + j;
        float bb = b2[c];
#pragma unroll
        for (int i = 0; i < 4; ++i) {
            int e = 4 * ty + i;
            float ms = acc[i][j] + bb;
            sms[e * 132 + c] = ms;
            if (e < nval) atomicAdd(&g_agg_s[sdst[e] * 128 + c], ms);
        }
    }
    __syncthreads();

    // ---- gates: sigmoid(ms @ Wg + bg), 512 tasks ----
    for (int q = tid; q < 512; q += 256) {
        int e = q >> 4, w = q & 15;
        float g = bg[w];
        for (int c = 0; c < 128; ++c)
            g = fmaf(sms[e * 132 + c], Wg[c * 16 + w], g);
        sg[e * 16 + w] = sigmoidf_(g);
    }
    __syncthreads();

    // ---- v projection * gate, scatter-add, 1536 tasks ----
    for (int q = tid; q < 1536; q += 256) {
        int e  = q / 48;
        int r  = q - e * 48;
        int w  = r / 3;
        int cc = r - w * 3;
        float a = 0.0f;
#pragma unroll
        for (int j = 0; j < 33; ++j)
            a = fmaf(sv[e * 100 + j * 3 + cc], Wv[j * 16 + w], a);
        a *= sg[e * 16 + w];
        if (e < nval) atomicAdd(&g_agg_v[sdst[e] * 48 + r], a);
    }
}

// ---------------------------------------------------------------------------
// Node update kernel: 8 nodes per block, 128 threads (one per output column).
//   x = [s(128), agg_s(128), vn(32)]  (vn from [v, agg_v], 32 rows)
//   ds = silu(x@W1+b1)@W2+b2 ; gate = sigmoid(ds@Wg+bg)
//   s_out = LN(s+ds) ; v_out = v + gate*(v_in@Wv)
// ---------------------------------------------------------------------------
__global__ __launch_bounds__(128) void node_kernel(
    const float* __restrict__ s, const float* __restrict__ v,
    const float* __restrict__ W1, const float* __restrict__ b1,
    const float* __restrict__ W2, const float* __restrict__ b2,
    const float* __restrict__ Wv, const float* __restrict__ Wg,
    const float* __restrict__ bg, const float* __restrict__ lng,
    const float* __restrict__ lnb,
    float* __restrict__ out_s, float* __restrict__ out_v, int n)
{
    __shared__ float xu[8][292];
    __shared__ float vin[8][96];
    __shared__ float tt[8][128];
    __shared__ float dsm[8][132];
    __shared__ float gate[8][16];
    __shared__ float rsum[8][4], rsq[8][4];

    const int tid = threadIdx.x;
    const int n0 = blockIdx.x * 8;

    for (int idx = tid; idx < 8 * 256; idx += 128) {
        int i = idx >> 8, k = idx & 255;
        int nd = min(n0 + i, n - 1);
        xu[i][k] = (k < 128) ? s[nd * 128 + k] : g_agg_s[nd * 128 + (k - 128)];
    }
    for (int idx = tid; idx < 8 * 96; idx += 128) {
        int i = idx / 96, k = idx - i * 96;
        int nd = min(n0 + i, n - 1);
        vin[i][k] = (k < 48) ? v[nd * 48 + k] : g_agg_v[nd * 48 + (k - 48)];
    }
    __syncthreads();
    for (int idx = tid; idx < 8 * 32; idx += 128) {
        int i = idx >> 5, j = idx & 31;
        float a = vin[i][j * 3], b = vin[i][j * 3 + 1], c = vin[i][j * 3 + 2];
        xu[i][256 + j] = sqrtf(fmaxf(a * a + b * b + c * c, 1e-8f));
    }
    __syncthreads();

    const int c = tid;
    float acc[8];
    {
        float bb = b1[c];
#pragma unroll
        for (int i = 0; i < 8; ++i) acc[i] = bb;
    }
    for (int k = 0; k < 288; ++k) {
        float w = W1[k * 128 + c];
#pragma unroll
        for (int i = 0; i < 8; ++i) acc[i] = fmaf(xu[i][k], w, acc[i]);
    }
#pragma unroll
    for (int i = 0; i < 8; ++i) {
        float h = acc[i];
        tt[i][c] = h * sigmoidf_(h);
    }
    __syncthreads();

    float acc2[8];
    {
        float bb = b2[c];
#pragma unroll
        for (int i = 0; i < 8; ++i) acc2[i] = bb;
    }
    for (int k = 0; k < 128; ++k) {
        float w = W2[k * 128 + c];
#pragma unroll
        for (int i = 0; i < 8; ++i) acc2[i] = fmaf(tt[i][k], w, acc2[i]);
    }
#pragma unroll
    for (int i = 0; i < 8; ++i) dsm[i][c] = acc2[i];
    __syncthreads();

    // gate: one (node, w) task per thread
    {
        int i = tid >> 4, w = tid & 15;
        float g = bg[w];
        for (int cc = 0; cc < 128; ++cc)
            g = fmaf(dsm[i][cc], Wg[cc * 16 + w], g);
        gate[i][w] = sigmoidf_(g);
    }

    // LayerNorm partial reduction
    float val[8];
#pragma unroll
    for (int i = 0; i < 8; ++i) {
        int nd = min(n0 + i, n - 1);
        val[i] = s[nd * 128 + c] + acc2[i];
    }
    const int lane = tid & 31, wq = tid >> 5;
    float psum[8], psq[8];
#pragma unroll
    for (int i = 0; i < 8; ++i) { psum[i] = val[i]; psq[i] = val[i] * val[i]; }
#pragma unroll
    for (int off = 16; off > 0; off >>= 1) {
#pragma unroll
        for (int i = 0; i < 8; ++i) {
            psum[i] += __shfl_xor_sync(0xffffffffu, psum[i], off);
            psq[i]  += __shfl_xor_sync(0xffffffffu, psq[i],  off);
        }
    }
    if (lane == 0) {
#pragma unroll
        for (int i = 0; i < 8; ++i) { rsum[i][wq] = psum[i]; rsq[i][wq] = psq[i]; }
    }
    __syncthreads();

#pragma unroll
    for (int i = 0; i < 8; ++i) {
        if (n0 + i >= n) continue;
        float sum = rsum[i][0] + rsum[i][1] + rsum[i][2] + rsum[i][3];
        float sq  = rsq[i][0] + rsq[i][1] + rsq[i][2] + rsq[i][3];
        float mu  = sum * (1.0f / 128.0f);
        float var = sq * (1.0f / 128.0f) - mu * mu;
        float o = (val[i] - mu) * rsqrtf(var + 1e-5f) * lng[c] + lnb[c];
        out_s[(n0 + i) * 128 + c] = o;
    }

    // v_out: 384 tasks
    for (int q = tid; q < 8 * 48; q += 128) {
        int i = q / 48, r = q - i * 48;
        if (n0 + i >= n) continue;
        int w = r / 3, cc = r - w * 3;
        float a = 0.0f;
#pragma unroll
        for (int j = 0; j < 32; ++j)
            a = fmaf(vin[i][j * 3 + cc], Wv[j * 16 + w], a);
        a *= gate[i][w];
        out_v[(n0 + i) * 48 + r] = v[(n0 + i) * 48 + r] + a;
    }
}

// ---------------------------------------------------------------------------
extern "C" void kernel_launch(void* const* d_in, const int* in_sizes, int n_in,
                              void* d_out, int out_size)
{
    const float* s      = (const float*)d_in[0];
    const float* v      = (const float*)d_in[1];
    const int*   ei     = (const int*)  d_in[2];
    const float* es     = (const float*)d_in[3];
    const float* ev     = (const float*)d_in[4];
    const float* mW1    = (const float*)d_in[5];
    const float* mb1    = (const float*)d_in[6];
    const float* mW2    = (const float*)d_in[7];
    const float* mb2    = (const float*)d_in[8];
    const float* mWv    = (const float*)d_in[9];
    const float* mWg    = (const float*)d_in[10];
    const float* mbg    = (const float*)d_in[11];
    const float* uW1    = (const float*)d_in[12];
    const float* ub1    = (const float*)d_in[13];
    const float* uW2    = (const float*)d_in[14];
    const float* ub2    = (const float*)d_in[15];
    const float* uWv    = (const float*)d_in[16];
    const float* uWg    = (const float*)d_in[17];
    const float* ubg    = (const float*)d_in[18];
    const float* lng    = (const float*)d_in[19];
    const float* lnb    = (const float*)d_in[20];

    const int n = in_sizes[0] / 128;
    const int E = in_sizes[2] / 2;

    float* out_s = (float*)d_out;
    float* out_v = out_s + (size_t)n * 128;

    cudaFuncSetAttribute(edge_kernel,
                         cudaFuncAttributeMaxDynamicSharedMemorySize,
                         EDGE_SMEM_BYTES);

    zero_kernel<<<(n * 176 + 255) / 256, 256>>>(n);

    edge_kernel<<<(E + 31) / 32, 256, EDGE_SMEM_BYTES>>>(
        s, v, ei, es, ev, mW1, mb1, mW2, mb2, mWv, mWg, mbg, E);

    node_kernel<<<(n + 7) / 8, 128>>>(
        s, v, uW1, ub1, uW2, ub2, uWv, uWg, ubg, lng, lnb,
        out_s, out_v, n);
}